// round 13
// baseline (speedup 1.0000x reference)
#include <cuda_runtime.h>

typedef unsigned long long ull;

#define HW 512
#define IMG (512 * 512)

// transformed weights: 64 ch x 9 rows x 4 floats (G0..G3) = 144B/ch -> 9 LDC.128
__constant__ __align__(16) float c_wT[64 * 36];
__device__ float d_scratch[64 * 36];

__device__ __forceinline__ ull pk(float lo, float hi) {
    ull r;
    asm("mov.b64 %0, {%1,%2};" : "=l"(r) : "f"(lo), "f"(hi));
    return r;
}
__device__ __forceinline__ ull ffma2(ull a, ull b, ull c) {
    ull d;
    asm("fma.rn.f32x2 %0, %1, %2, %3;" : "=l"(d) : "l"(a), "l"(b), "l"(c));
    return d;
}
__device__ __forceinline__ ull fadd2(ull a, ull b) {
    ull d;
    asm("add.rn.f32x2 %0, %1, %2;" : "=l"(d) : "l"(a), "l"(b));
    return d;
}
__device__ __forceinline__ ull neg2(ull a) { return a ^ 0x8000000080000000ULL; }
// (a.lo, b.lo)
__device__ __forceinline__ ull lolo(ull a, ull b) {
    ull r;
    asm("{\n\t.reg .b32 al, ah, bl, bh;\n\t"
        "mov.b64 {al, ah}, %1;\n\tmov.b64 {bl, bh}, %2;\n\t"
        "mov.b64 %0, {al, bl};\n\t}" : "=l"(r) : "l"(a), "l"(b));
    return r;
}
// (a.hi, b.hi)
__device__ __forceinline__ ull hihi(ull a, ull b) {
    ull r;
    asm("{\n\t.reg .b32 al, ah, bl, bh;\n\t"
        "mov.b64 {al, ah}, %1;\n\tmov.b64 {bl, bh}, %2;\n\t"
        "mov.b64 %0, {ah, bh};\n\t}" : "=l"(r) : "l"(a), "l"(b));
    return r;
}

// Winograd F(2,3) weight transform: G = [g0, (g0+g1+g2)/2, (g0-g1+g2)/2, g2]
__global__ void prep_weights(const float* __restrict__ wm) {
    int i = blockIdx.x * blockDim.x + threadIdx.x;   // over 64*9 tap-rows
    if (i < 64 * 9) {
        int c = i / 9, r = i - c * 9;
        float g0 = wm[c * 27 + r * 3 + 0];
        float g1 = wm[c * 27 + r * 3 + 1];
        float g2 = wm[c * 27 + r * 3 + 2];
        float* o = d_scratch + c * 36 + r * 4;
        o[0] = g0;
        o[1] = (g0 + g1 + g2) * 0.5f;
        o[2] = (g0 - g1 + g2) * 0.5f;
        o[3] = g2;
    }
}

// m-domain accumulate for one tap-row (both tile-sets), weights from 1 LDC.128
#define MROW(R) { \
    float4 g = gw[R]; \
    ull G0 = pk(g.x, g.x), G1 = pk(g.y, g.y); \
    ull G2 = pk(g.z, g.z), G3 = pk(g.w, g.w); \
    M0A = ffma2(G0, tA0[R], M0A); M1A = ffma2(G1, tA1[R], M1A); \
    M2A = ffma2(G2, tA2[R], M2A); M3A = ffma2(G3, tA3[R], M3A); \
    M0B = ffma2(G0, tB0[R], M0B); M1B = ffma2(G1, tB1[R], M1B); \
    M2B = ffma2(G2, tB2[R], M2B); M3B = ffma2(G3, tB3[R], M3B); }

#define CHBODY(M0Aseed, M1seed, M3Bseed) \
    const float4* gw = (const float4*)(c_wT + c * 36); \
    ull M0A = (M0Aseed), M1A = (M1seed), M2A = 0ULL, M3A = 0ULL; \
    ull M0B = 0ULL, M1B = (M1seed), M2B = 0ULL, M3B = (M3Bseed); \
    MROW(0) MROW(1) MROW(2) MROW(3) MROW(4) \
    MROW(5) MROW(6) MROW(7) MROW(8) \
    ull y0A = fadd2(M0A, fadd2(M1A, M2A)); \
    ull y1A = fadd2(M1A, neg2(fadd2(M2A, M3A))); \
    ull y0B = fadd2(M0B, fadd2(M1B, M2B)); \
    ull y1B = fadd2(M1B, neg2(fadd2(M2B, M3B))); \
    ulonglong2 r01, r23; \
    r01.x = lolo(y0A, y1A); r01.y = hihi(y0A, y1A); \
    r23.x = lolo(y0B, y1B); r23.y = hihi(y0B, y1B); \
    float* op = outp + (size_t)c * IMG; \
    *reinterpret_cast<ulonglong2*>(op)     = r01; \
    *reinterpret_cast<ulonglong2*>(op + 4) = r23;

__global__ void __launch_bounds__(128, 2) conv_main(
    const float* __restrict__ x,   // [8,3,512,512]
    const float* __restrict__ ei,  // [8,192]
    const float* __restrict__ bm,  // [64]
    const float* __restrict__ we,  // [64,3,3,3]
    const float* __restrict__ be,  // [64]
    float* __restrict__ out)       // [8,64,512,512]
{
    __shared__ __align__(16) float xs[3][6][260];   // rows h0-1..h0+4, cols w0-1..w0+256
    __shared__ ull sBase[64], sAtab[64], sDtab[64], sZtab[64];
    __shared__ float sCT[64], sCB[64], sTL[64], sTR[64], sBL[64], sBR[64];

    const int tid = threadIdx.x, lane = tid & 31, wid = tid >> 5;
    const int cx = blockIdx.x, ty = blockIdx.y, b = blockIdx.z;
    const int w0 = cx * 256, h0 = ty * 4;

    // ---- stage input patch (zero padded) ----
    for (int i = tid; i < 3 * 6 * 258; i += 128) {
        int ci = i / 1548;
        int rem = i - ci * 1548;
        int rr = rem / 258, j = rem - rr * 258;
        int gh = h0 - 1 + rr, gw_ = w0 - 1 + j;
        float v = 0.f;
        if ((unsigned)gh < 512u && (unsigned)gw_ < 512u)
            v = x[((b * 3 + ci) * HW + gh) * HW + gw_];
        xs[ci][rr][j] = v;
    }

    // ---- per-channel extra-term scalars ----
    if (tid < 64) {
        int c = tid;
        float S = 0, rT = 0, rB = 0, kL = 0, kR = 0;
        float tTL = 0, tTR = 0, tBL = 0, tBR = 0;
        #pragma unroll
        for (int e = 0; e < 3; e++) {
            float v = __ldg(ei + b * 192 + c * 3 + e);
            const float* wq = we + (c * 3 + e) * 9;
            #pragma unroll
            for (int ky = 0; ky < 3; ky++) {
                #pragma unroll
                for (int kx = 0; kx < 3; kx++) {
                    float t = v * __ldg(wq + ky * 3 + kx);
                    S += t;
                    if (ky == 0) rT += t;
                    if (ky == 2) rB += t;
                    if (kx == 0) kL += t;
                    if (kx == 2) kR += t;
                    if (ky == 0 && kx == 0) tTL += t;
                    if (ky == 0 && kx == 2) tTR += t;
                    if (ky == 2 && kx == 0) tBL += t;
                    if (ky == 2 && kx == 2) tBR += t;
                }
            }
        }
        float base = __ldg(bm + c) + __ldg(be + c) + S;
        sBase[c] = pk(base, base);
        sAtab[c] = pk(-kL, 0.f);    // seeds M0A.lo: only y0 of tile0 (px 0)
        sDtab[c] = pk(0.f, kR);     // seeds M3B.hi: y1 -= M3 => contributes -kR at px 511
        sZtab[c] = 0ULL;
        sCT[c] = -rT; sCB[c] = -rB;
        sTL[c] = tTL; sTR[c] = tTR; sBL[c] = tBL; sBR[c] = tBR;
    }
    __syncthreads();

    // ---- one-time Winograd input transform: t window in registers ----
    // thread covers px p..p+7, p = w0 + lane*8; v[0..9] = x[p-1..p+8]
    ull tA0[9], tA1[9], tA2[9], tA3[9];
    ull tB0[9], tB1[9], tB2[9], tB3[9];
    #pragma unroll
    for (int ci = 0; ci < 3; ci++) {
        #pragma unroll
        for (int dy = 0; dy < 3; dy++) {
            const float* p = &xs[ci][wid + dy][lane * 8];
            float4 a = *reinterpret_cast<const float4*>(p);
            float4 bq = *reinterpret_cast<const float4*>(p + 4);
            float2 cq = *reinterpret_cast<const float2*>(p + 8);
            float v0 = a.x, v1 = a.y, v2 = a.z, v3 = a.w;
            float v4 = bq.x, v5 = bq.y, v6 = bq.z, v7 = bq.w;
            float v8 = cq.x, v9 = cq.y;
            int r = ci * 3 + dy;
            tA0[r] = pk(v0 - v2, v2 - v4);
            tA1[r] = pk(v1 + v2, v3 + v4);
            tA2[r] = pk(v2 - v1, v4 - v3);
            tA3[r] = pk(v1 - v3, v3 - v5);
            tB0[r] = pk(v4 - v6, v6 - v8);
            tB1[r] = pk(v5 + v6, v7 + v8);
            tB2[r] = pk(v6 - v5, v8 - v7);
            tB3[r] = pk(v5 - v7, v7 - v9);
        }
    }

    const int h = h0 + wid;
    const bool isL = (cx == 0) && (lane == 0);
    const bool isR = (cx == 1) && (lane == 31);
    const bool top = (h == 0), bot = (h == HW - 1);

    const ull* aptr = isL ? sAtab : sZtab;
    const ull* dptr = isR ? sDtab : sZtab;

    float* outp = out + (((size_t)b * 64) * HW + h) * HW + w0 + lane * 8;

    if (!(top | bot)) {
        #pragma unroll 1
        for (int c = 0; c < 64; c++) {
            CHBODY(aptr[c], sBase[c], dptr[c])
        }
    } else {
        const float* rowc  = top ? sCT : sCB;
        const float* cornL = top ? sTL : sBL;
        const float* cornR = top ? sTR : sBR;
        #pragma unroll 1
        for (int c = 0; c < 64; c++) {
            float adj = rowc[c];
            ull m1seed = fadd2(sBase[c], pk(adj, adj));
            float cl = isL ? cornL[c] : 0.f;
            float cr = isR ? cornR[c] : 0.f;
            ull m0aseed = fadd2(aptr[c], pk(cl, 0.f));
            ull m3bseed = fadd2(dptr[c], pk(0.f, -cr));
            CHBODY(m0aseed, m1seed, m3bseed)
        }
    }
}

extern "C" void kernel_launch(void* const* d_in, const int* in_sizes, int n_in,
                              void* d_out, int out_size)
{
    const float* x  = (const float*)d_in[0];
    const float* ei = (const float*)d_in[1];
    const float* wm = (const float*)d_in[2];
    const float* bm = (const float*)d_in[3];
    const float* we = (const float*)d_in[4];
    const float* be = (const float*)d_in[5];
    float* out = (float*)d_out;

    prep_weights<<<(64 * 9 + 255) / 256, 256>>>(wm);

    void* scratch_ptr = nullptr;
    cudaGetSymbolAddress(&scratch_ptr, d_scratch);
    cudaMemcpyToSymbolAsync(c_wT, scratch_ptr, sizeof(float) * 64 * 36, 0,
                            cudaMemcpyDeviceToDevice, 0);

    dim3 grid(2, 128, 8);   // 2 col-blocks x 128 row-blocks x 8 batches = 2048 CTAs
    conv_main<<<grid, 128>>>(x, ei, bm, we, be, out);
}